// round 7
// baseline (speedup 1.0000x reference)
#include <cuda_runtime.h>
#include <cuda_bf16.h>
#include <math.h>
#include <stdint.h>

// x[131072,256] @ W1[256,512] -> tanh -> @W2[512,512] -> tanh -> @W3[512,128] (+biases).
// Fixed-point loop converges to F(x) within ~4e-7 abs => output == MLP forward.
constexpr int BATCH = 131072;
constexpr int DIN   = 256;
constexpr int HID   = 512;
constexpr int DOUT  = 128;

// ---------- device scratch (static; no runtime allocation allowed) ----------
__device__ __align__(256) __nv_bfloat16 g_xh[(size_t)BATCH * DIN];
__device__ __align__(256) __nv_bfloat16 g_xl[(size_t)BATCH * DIN];
__device__ __align__(256) __nv_bfloat16 g_h1h[(size_t)BATCH * HID];
__device__ __align__(256) __nv_bfloat16 g_h1l[(size_t)BATCH * HID];
__device__ __align__(256) __nv_bfloat16 g_h2h[(size_t)BATCH * HID];
__device__ __align__(256) __nv_bfloat16 g_h2l[(size_t)BATCH * HID];

constexpr size_t W1_OFF = 0;
constexpr size_t W1_SZ  = (size_t)HID * DIN;
constexpr size_t W2_OFF = W1_OFF + W1_SZ;
constexpr size_t W2_SZ  = (size_t)HID * HID;
constexpr size_t W3_OFF = W2_OFF + W2_SZ;
constexpr size_t W3_SZ  = (size_t)DOUT * HID;
__device__ __align__(256) __nv_bfloat16 g_wh[W1_SZ + W2_SZ + W3_SZ];
__device__ __align__(256) __nv_bfloat16 g_wl[W1_SZ + W2_SZ + W3_SZ];

// ---------- PTX helpers (compute_103-safe: NO tcgen05) ----------
__device__ __forceinline__ uint32_t smem_u32(const void* p) {
    uint32_t a;
    asm("{ .reg .u64 t; cvta.to.shared.u64 t, %1; cvt.u32.u64 %0, t; }" : "=r"(a) : "l"(p));
    return a;
}
__device__ __forceinline__ void cp16(uint32_t dst, const void* src) {
    asm volatile("cp.async.cg.shared.global [%0], [%1], 16;" :: "r"(dst), "l"(src));
}
__device__ __forceinline__ void cp_commit() { asm volatile("cp.async.commit_group;"); }
__device__ __forceinline__ void cp_wait1()  { asm volatile("cp.async.wait_group 1;"); }

__device__ __forceinline__ void ldsm4(uint32_t* r, uint32_t addr) {
    asm volatile("ldmatrix.sync.aligned.m8n8.x4.shared.b16 {%0,%1,%2,%3}, [%4];"
                 : "=r"(r[0]), "=r"(r[1]), "=r"(r[2]), "=r"(r[3]) : "r"(addr));
}
__device__ __forceinline__ void mma16816(float* d, const uint32_t* a, const uint32_t* b) {
    asm volatile("mma.sync.aligned.m16n8k16.row.col.f32.bf16.bf16.f32 "
                 "{%0,%1,%2,%3}, {%4,%5,%6,%7}, {%8,%9}, {%0,%1,%2,%3};"
                 : "+f"(d[0]), "+f"(d[1]), "+f"(d[2]), "+f"(d[3])
                 : "r"(a[0]), "r"(a[1]), "r"(a[2]), "r"(a[3]), "r"(b[0]), "r"(b[1]));
}

// fast accurate tanh: (e-1)/(e+1), e = 2^(2x*log2e). abs err ~1e-7.
__device__ __forceinline__ float tanh_fast(float x) {
    float xc = fminf(fmaxf(x, -15.0f), 15.0f);
    float e;
    asm("ex2.approx.f32 %0, %1;" : "=f"(e) : "f"(xc * 2.885390081777927f));
    float r;
    asm("rcp.approx.f32 %0, %1;" : "=f"(r) : "f"(e + 1.0f));
    return (e - 1.0f) * r;
}

__device__ __forceinline__ void split2(float v0, float v1, uint32_t& hi, uint32_t& lo) {
    __nv_bfloat16 h0 = __float2bfloat16(v0);
    __nv_bfloat16 h1 = __float2bfloat16(v1);
    __nv_bfloat16 l0 = __float2bfloat16(v0 - __bfloat162float(h0));
    __nv_bfloat16 l1 = __float2bfloat16(v1 - __bfloat162float(h1));
    hi = (uint32_t)__bfloat16_as_ushort(h0) | ((uint32_t)__bfloat16_as_ushort(h1) << 16);
    lo = (uint32_t)__bfloat16_as_ushort(l0) | ((uint32_t)__bfloat16_as_ushort(l1) << 16);
}

// ---------- prep kernels ----------
__global__ void prep_x(const float* __restrict__ x) {
    size_t i = ((size_t)blockIdx.x * blockDim.x + threadIdx.x) * 4;
    float4 v = *reinterpret_cast<const float4*>(x + i);
    uint2 hi, lo;
    split2(v.x, v.y, hi.x, lo.x);
    split2(v.z, v.w, hi.y, lo.y);
    *reinterpret_cast<uint2*>(&g_xh[i]) = hi;
    *reinterpret_cast<uint2*>(&g_xl[i]) = lo;
}
__global__ void prep_w(const float* __restrict__ W, int K, int N, size_t dstOff) {
    int idx = blockIdx.x * blockDim.x + threadIdx.x;   // idx = n*K + k
    if (idx >= K * N) return;
    int n = idx / K;
    int k = idx - n * K;
    float v = W[(size_t)k * N + n];
    __nv_bfloat16 h = __float2bfloat16(v);
    g_wh[dstOff + idx] = h;
    g_wl[dstOff + idx] = __float2bfloat16(v - __bfloat162float(h));
}

// ---------- main GEMM: 256x128 tile, BK=32, 3-stage cp.async, 3-term split-bf16 ----------
// SMEM per stage: AH 16KB | AL 16KB | BH 8KB | BL 8KB = 48KB; 3 stages = 144KB.
constexpr uint32_t OFF_AH = 0;
constexpr uint32_t OFF_AL = 16384;
constexpr uint32_t OFF_BH = 32768;
constexpr uint32_t OFF_BL = 40960;
constexpr uint32_t STAGE  = 49152;
constexpr int SMEM_TOTAL  = 3 * STAGE;   // 147456

template<bool TANH, bool FP32OUT>
__global__ __launch_bounds__(256, 1)
void gemm_hmma(int aSel, size_t wOff, const float* __restrict__ bias,
               int cSel, float* __restrict__ Cf, int N, int K)
{
    const __nv_bfloat16 *Ah, *Al;
    if      (aSel == 0) { Ah = g_xh;  Al = g_xl;  }
    else if (aSel == 1) { Ah = g_h1h; Al = g_h1l; }
    else                { Ah = g_h2h; Al = g_h2l; }
    __nv_bfloat16 *Ch = nullptr, *Cl = nullptr;
    if      (cSel == 1) { Ch = g_h1h; Cl = g_h1l; }
    else if (cSel == 2) { Ch = g_h2h; Cl = g_h2l; }
    const __nv_bfloat16* Wh = g_wh + wOff;
    const __nv_bfloat16* Wl = g_wl + wOff;

    extern __shared__ char smem[];
    const uint32_t sbase = smem_u32(smem);
    const int tid  = threadIdx.x;
    const int wid  = tid >> 5;
    const int lane = tid & 31;
    const int mBase = blockIdx.y * 256;
    const int nBase = blockIdx.x * 128;
    const int warpM = (wid >> 1) * 64;     // 4 warp-rows x 64
    const int warpN = (wid & 1) * 64;      // 2 warp-cols x 64
    const int NC = K / 32;

    // loader mapping: 16B chunks; row stride 64B (32 bf16)
    const int lr = tid >> 2;               // 0..63
    const int lj = tid & 3;                // 16B chunk within 64B row
    const uint32_t swj = (uint32_t)lj * 16;
    auto so = [&](uint32_t row) { return row * 64 + (swj ^ ((row & 6) << 3)); };

    auto loadChunk = [&](int kc, int s) {
        const uint32_t sb = sbase + (uint32_t)s * STAGE;
        const size_t colOff = (size_t)kc * 32 + lj * 8;
        #pragma unroll
        for (int i = 0; i < 4; i++) {          // A: 256 rows
            uint32_t row = (uint32_t)(lr + i * 64);
            const size_t g = (size_t)(mBase + row) * K + colOff;
            cp16(sb + OFF_AH + so(row), Ah + g);
            cp16(sb + OFF_AL + so(row), Al + g);
        }
        #pragma unroll
        for (int i = 0; i < 2; i++) {          // B: 128 rows
            uint32_t row = (uint32_t)(lr + i * 64);
            const size_t g = (size_t)(nBase + row) * K + colOff;
            cp16(sb + OFF_BH + so(row), Wh + g);
            cp16(sb + OFF_BL + so(row), Wl + g);
        }
    };

    float acc[4][8][4];
    #pragma unroll
    for (int i = 0; i < 4; i++)
        #pragma unroll
        for (int j = 0; j < 8; j++)
            #pragma unroll
            for (int q = 0; q < 4; q++) acc[i][j][q] = 0.0f;

    const int lrow = lane & 15, lhi = lane >> 4;

    loadChunk(0, 0); cp_commit();
    loadChunk(1, 1); cp_commit();

    for (int c = 0; c < NC; c++) {
        cp_wait1();
        __syncthreads();
        if (c + 2 < NC) loadChunk(c + 2, (c + 2) % 3);
        cp_commit();

        const uint32_t sb = sbase + (uint32_t)(c % 3) * STAGE;
        #pragma unroll
        for (int ks = 0; ks < 2; ks++) {
            const uint32_t colb = ks * 32 + lhi * 16;
            uint32_t ah[4][4], al[4][4], bb[8][2];
            #pragma unroll
            for (int i = 0; i < 4; i++) {
                uint32_t row = warpM + i * 16 + lrow;
                uint32_t off = row * 64 + (colb ^ ((row & 6) << 3));
                ldsm4(ah[i], sb + OFF_AH + off);
                ldsm4(al[i], sb + OFF_AL + off);
            }
            #pragma unroll
            for (int p = 0; p < 4; p++) {
                uint32_t row = warpN + p * 16 + lrow;
                uint32_t off = row * 64 + (colb ^ ((row & 6) << 3));
                uint32_t r[4];
                ldsm4(r, sb + OFF_BH + off);
                bb[2 * p][0] = r[0]; bb[2 * p][1] = r[2];
                bb[2 * p + 1][0] = r[1]; bb[2 * p + 1][1] = r[3];
            }
            #pragma unroll
            for (int i = 0; i < 4; i++)
                #pragma unroll
                for (int j = 0; j < 8; j++) mma16816(acc[i][j], ah[i], bb[j]);
            #pragma unroll
            for (int i = 0; i < 4; i++)
                #pragma unroll
                for (int j = 0; j < 8; j++) mma16816(acc[i][j], al[i], bb[j]);
            #pragma unroll
            for (int p = 0; p < 4; p++) {
                uint32_t row = warpN + p * 16 + lrow;
                uint32_t off = row * 64 + (colb ^ ((row & 6) << 3));
                uint32_t r[4];
                ldsm4(r, sb + OFF_BL + off);
                bb[2 * p][0] = r[0]; bb[2 * p][1] = r[2];
                bb[2 * p + 1][0] = r[1]; bb[2 * p + 1][1] = r[3];
            }
            #pragma unroll
            for (int i = 0; i < 4; i++)
                #pragma unroll
                for (int j = 0; j < 8; j++) mma16816(acc[i][j], ah[i], bb[j]);
        }
    }

    // ---------- epilogue ----------
    #pragma unroll
    for (int i = 0; i < 4; i++) {
        const int m0 = mBase + warpM + i * 16 + (lane >> 2);
        #pragma unroll
        for (int j = 0; j < 8; j++) {
            const int n = nBase + warpN + j * 8 + (lane & 3) * 2;
            const float2 bb2 = *reinterpret_cast<const float2*>(&bias[n]);
            float v00 = acc[i][j][0] + bb2.x, v01 = acc[i][j][1] + bb2.y;
            float v10 = acc[i][j][2] + bb2.x, v11 = acc[i][j][3] + bb2.y;
            if (TANH) {
                v00 = tanh_fast(v00); v01 = tanh_fast(v01);
                v10 = tanh_fast(v10); v11 = tanh_fast(v11);
            }
            if (FP32OUT) {
                *reinterpret_cast<float2*>(&Cf[(size_t)m0 * N + n])       = make_float2(v00, v01);
                *reinterpret_cast<float2*>(&Cf[(size_t)(m0 + 8) * N + n]) = make_float2(v10, v11);
            } else {
                uint32_t hi, lo;
                split2(v00, v01, hi, lo);
                *reinterpret_cast<uint32_t*>(&Ch[(size_t)m0 * N + n]) = hi;
                *reinterpret_cast<uint32_t*>(&Cl[(size_t)m0 * N + n]) = lo;
                split2(v10, v11, hi, lo);
                *reinterpret_cast<uint32_t*>(&Ch[(size_t)(m0 + 8) * N + n]) = hi;
                *reinterpret_cast<uint32_t*>(&Cl[(size_t)(m0 + 8) * N + n]) = lo;
            }
        }
    }
}

// ---------- launch ----------
extern "C" void kernel_launch(void* const* d_in, const int* in_sizes, int n_in,
                              void* d_out, int out_size)
{
    const float* x  = (const float*)d_in[0];
    const float* W1 = (const float*)d_in[1];
    const float* b1 = (const float*)d_in[2];
    const float* W2 = (const float*)d_in[3];
    const float* b2 = (const float*)d_in[4];
    const float* W3 = (const float*)d_in[5];
    const float* b3 = (const float*)d_in[6];
    float* out = (float*)d_out;

    prep_x<<<(int)((size_t)BATCH * DIN / 4 / 256), 256>>>(x);
    prep_w<<<(int)((W1_SZ + 255) / 256), 256>>>(W1, DIN, HID, W1_OFF);
    prep_w<<<(int)((W2_SZ + 255) / 256), 256>>>(W2, HID, HID, W2_OFF);
    prep_w<<<(int)((W3_SZ + 255) / 256), 256>>>(W3, HID, DOUT, W3_OFF);

    cudaFuncSetAttribute(gemm_hmma<true,  false>,
                         cudaFuncAttributeMaxDynamicSharedMemorySize, SMEM_TOTAL);
    cudaFuncSetAttribute(gemm_hmma<false, true>,
                         cudaFuncAttributeMaxDynamicSharedMemorySize, SMEM_TOTAL);

    dim3 grid12(HID / 128, BATCH / 256);   // (4, 512)
    dim3 grid3 (DOUT / 128, BATCH / 256);  // (1, 512)

    gemm_hmma<true,  false><<<grid12, 256, SMEM_TOTAL>>>(0, W1_OFF, b1, 1, nullptr, HID, DIN);
    gemm_hmma<true,  false><<<grid12, 256, SMEM_TOTAL>>>(1, W2_OFF, b2, 2, nullptr, HID, HID);
    gemm_hmma<false, true ><<<grid3,  256, SMEM_TOTAL>>>(2, W3_OFF, b3, 0, out, DOUT, HID);
}

// round 8
// speedup vs baseline: 1.0563x; 1.0563x over previous
#include <cuda_runtime.h>
#include <cuda_bf16.h>
#include <math.h>
#include <stdint.h>

// x[131072,256] @ W1[256,512] -> tanh -> @W2[512,512] -> tanh -> @W3[512,128] (+biases).
// Fixed-point loop converges to F(x) within ~4e-7 abs => output == MLP forward.
constexpr int BATCH = 131072;
constexpr int DIN   = 256;
constexpr int HID   = 512;
constexpr int DOUT  = 128;

// ---------- device scratch (static; no runtime allocation allowed) ----------
__device__ __align__(256) __nv_bfloat16 g_xh[(size_t)BATCH * DIN];
__device__ __align__(256) __nv_bfloat16 g_xl[(size_t)BATCH * DIN];
__device__ __align__(256) __nv_bfloat16 g_h1h[(size_t)BATCH * HID];
__device__ __align__(256) __nv_bfloat16 g_h1l[(size_t)BATCH * HID];
__device__ __align__(256) __nv_bfloat16 g_h2h[(size_t)BATCH * HID];
__device__ __align__(256) __nv_bfloat16 g_h2l[(size_t)BATCH * HID];

constexpr size_t W1_OFF = 0;
constexpr size_t W1_SZ  = (size_t)HID * DIN;
constexpr size_t W2_OFF = W1_OFF + W1_SZ;
constexpr size_t W2_SZ  = (size_t)HID * HID;
constexpr size_t W3_OFF = W2_OFF + W2_SZ;
constexpr size_t W3_SZ  = (size_t)DOUT * HID;
__device__ __align__(256) __nv_bfloat16 g_wh[W1_SZ + W2_SZ + W3_SZ];
__device__ __align__(256) __nv_bfloat16 g_wl[W1_SZ + W2_SZ + W3_SZ];

// ---------- PTX helpers (compute_103-safe: NO tcgen05) ----------
__device__ __forceinline__ uint32_t smem_u32(const void* p) {
    uint32_t a;
    asm("{ .reg .u64 t; cvta.to.shared.u64 t, %1; cvt.u32.u64 %0, t; }" : "=r"(a) : "l"(p));
    return a;
}
__device__ __forceinline__ void cp16(uint32_t dst, const void* src) {
    asm volatile("cp.async.cg.shared.global [%0], [%1], 16;" :: "r"(dst), "l"(src));
}
__device__ __forceinline__ void cp_commit() { asm volatile("cp.async.commit_group;"); }
__device__ __forceinline__ void cp_wait1()  { asm volatile("cp.async.wait_group 1;"); }

__device__ __forceinline__ void ldsm4(uint32_t* r, uint32_t addr) {
    asm volatile("ldmatrix.sync.aligned.m8n8.x4.shared.b16 {%0,%1,%2,%3}, [%4];"
                 : "=r"(r[0]), "=r"(r[1]), "=r"(r[2]), "=r"(r[3]) : "r"(addr));
}
__device__ __forceinline__ void mma16816(float* d, const uint32_t* a, const uint32_t* b) {
    asm volatile("mma.sync.aligned.m16n8k16.row.col.f32.bf16.bf16.f32 "
                 "{%0,%1,%2,%3}, {%4,%5,%6,%7}, {%8,%9}, {%0,%1,%2,%3};"
                 : "+f"(d[0]), "+f"(d[1]), "+f"(d[2]), "+f"(d[3])
                 : "r"(a[0]), "r"(a[1]), "r"(a[2]), "r"(a[3]), "r"(b[0]), "r"(b[1]));
}

// fast accurate tanh: (e-1)/(e+1), e = 2^(2x*log2e). abs err ~1e-7.
__device__ __forceinline__ float tanh_fast(float x) {
    float xc = fminf(fmaxf(x, -15.0f), 15.0f);
    float e;
    asm("ex2.approx.f32 %0, %1;" : "=f"(e) : "f"(xc * 2.885390081777927f));
    float r;
    asm("rcp.approx.f32 %0, %1;" : "=f"(r) : "f"(e + 1.0f));
    return (e - 1.0f) * r;
}

__device__ __forceinline__ void split2(float v0, float v1, uint32_t& hi, uint32_t& lo) {
    __nv_bfloat16 h0 = __float2bfloat16(v0);
    __nv_bfloat16 h1 = __float2bfloat16(v1);
    __nv_bfloat16 l0 = __float2bfloat16(v0 - __bfloat162float(h0));
    __nv_bfloat16 l1 = __float2bfloat16(v1 - __bfloat162float(h1));
    hi = (uint32_t)__bfloat16_as_ushort(h0) | ((uint32_t)__bfloat16_as_ushort(h1) << 16);
    lo = (uint32_t)__bfloat16_as_ushort(l0) | ((uint32_t)__bfloat16_as_ushort(l1) << 16);
}

// ---------- prep kernels ----------
__global__ void prep_x(const float* __restrict__ x) {
    size_t i = ((size_t)blockIdx.x * blockDim.x + threadIdx.x) * 4;
    float4 v = *reinterpret_cast<const float4*>(x + i);
    uint2 hi, lo;
    split2(v.x, v.y, hi.x, lo.x);
    split2(v.z, v.w, hi.y, lo.y);
    *reinterpret_cast<uint2*>(&g_xh[i]) = hi;
    *reinterpret_cast<uint2*>(&g_xl[i]) = lo;
}
__global__ void prep_w(const float* __restrict__ W, int K, int N, size_t dstOff) {
    int idx = blockIdx.x * blockDim.x + threadIdx.x;   // idx = n*K + k
    if (idx >= K * N) return;
    int n = idx / K;
    int k = idx - n * K;
    float v = W[(size_t)k * N + n];
    __nv_bfloat16 h = __float2bfloat16(v);
    g_wh[dstOff + idx] = h;
    g_wl[dstOff + idx] = __float2bfloat16(v - __bfloat162float(h));
}

// ---------- main GEMM: 256x128 tile, 512 threads (16 warps), BK=32, 3-stage cp.async ----------
// Warp grid: 8 (M) x 2 (N); warp tile 32x64; acc[2][8][4] = 64 fp32 regs/thread.
// SMEM per stage: AH 16KB | AL 16KB | BH 8KB | BL 8KB = 48KB; 3 stages = 144KB (1 CTA/SM).
// 16 warps/SM = 4/SMSP: same latency hiding as the 2x(256-thread) R3 config,
// with the 256-row tile's halved B-side L2 traffic.
constexpr uint32_t OFF_AH = 0;
constexpr uint32_t OFF_AL = 16384;
constexpr uint32_t OFF_BH = 32768;
constexpr uint32_t OFF_BL = 40960;
constexpr uint32_t STAGE  = 49152;
constexpr int SMEM_TOTAL  = 3 * STAGE;   // 147456

template<bool TANH, bool FP32OUT>
__global__ __launch_bounds__(512, 1)
void gemm_hmma(int aSel, size_t wOff, const float* __restrict__ bias,
               int cSel, float* __restrict__ Cf, int N, int K)
{
    const __nv_bfloat16 *Ah, *Al;
    if      (aSel == 0) { Ah = g_xh;  Al = g_xl;  }
    else if (aSel == 1) { Ah = g_h1h; Al = g_h1l; }
    else                { Ah = g_h2h; Al = g_h2l; }
    __nv_bfloat16 *Ch = nullptr, *Cl = nullptr;
    if      (cSel == 1) { Ch = g_h1h; Cl = g_h1l; }
    else if (cSel == 2) { Ch = g_h2h; Cl = g_h2l; }
    const __nv_bfloat16* Wh = g_wh + wOff;
    const __nv_bfloat16* Wl = g_wl + wOff;

    extern __shared__ char smem[];
    const uint32_t sbase = smem_u32(smem);
    const int tid  = threadIdx.x;
    const int wid  = tid >> 5;             // 0..15
    const int lane = tid & 31;
    const int mBase = blockIdx.y * 256;
    const int nBase = blockIdx.x * 128;
    const int warpM = (wid >> 1) * 32;     // 8 warp-rows x 32
    const int warpN = (wid & 1) * 64;      // 2 warp-cols x 64
    const int NC = K / 32;

    // loader mapping: 512 threads, 16B chunks, row stride 64B (32 bf16)
    const int lr = tid >> 2;               // 0..127
    const int lj = tid & 3;                // 16B chunk within 64B row
    const uint32_t swj = (uint32_t)lj * 16;
    auto so = [&](uint32_t row) { return row * 64 + (swj ^ ((row & 6) << 3)); };

    auto loadChunk = [&](int kc, int s) {
        const uint32_t sb = sbase + (uint32_t)s * STAGE;
        const size_t colOff = (size_t)kc * 32 + lj * 8;
        #pragma unroll
        for (int i = 0; i < 2; i++) {          // A: 256 rows, 128 per pass
            uint32_t row = (uint32_t)(lr + i * 128);
            const size_t g = (size_t)(mBase + row) * K + colOff;
            cp16(sb + OFF_AH + so(row), Ah + g);
            cp16(sb + OFF_AL + so(row), Al + g);
        }
        {                                      // B: 128 rows, one pass
            uint32_t row = (uint32_t)lr;
            const size_t g = (size_t)(nBase + row) * K + colOff;
            cp16(sb + OFF_BH + so(row), Wh + g);
            cp16(sb + OFF_BL + so(row), Wl + g);
        }
    };

    float acc[2][8][4];
    #pragma unroll
    for (int i = 0; i < 2; i++)
        #pragma unroll
        for (int j = 0; j < 8; j++)
            #pragma unroll
            for (int q = 0; q < 4; q++) acc[i][j][q] = 0.0f;

    const int lrow = lane & 15, lhi = lane >> 4;

    loadChunk(0, 0); cp_commit();
    loadChunk(1, 1); cp_commit();

    for (int c = 0; c < NC; c++) {
        cp_wait1();
        __syncthreads();
        if (c + 2 < NC) loadChunk(c + 2, (c + 2) % 3);
        cp_commit();

        const uint32_t sb = sbase + (uint32_t)(c % 3) * STAGE;
        #pragma unroll
        for (int ks = 0; ks < 2; ks++) {
            const uint32_t colb = ks * 32 + lhi * 16;
            uint32_t ah[2][4], al[2][4], bb[8][2];
            #pragma unroll
            for (int i = 0; i < 2; i++) {
                uint32_t row = warpM + i * 16 + lrow;
                uint32_t off = row * 64 + (colb ^ ((row & 6) << 3));
                ldsm4(ah[i], sb + OFF_AH + off);
                ldsm4(al[i], sb + OFF_AL + off);
            }
            #pragma unroll
            for (int p = 0; p < 4; p++) {
                uint32_t row = warpN + p * 16 + lrow;
                uint32_t off = row * 64 + (colb ^ ((row & 6) << 3));
                uint32_t r[4];
                ldsm4(r, sb + OFF_BH + off);
                bb[2 * p][0] = r[0]; bb[2 * p][1] = r[2];
                bb[2 * p + 1][0] = r[1]; bb[2 * p + 1][1] = r[3];
            }
            #pragma unroll
            for (int i = 0; i < 2; i++)
                #pragma unroll
                for (int j = 0; j < 8; j++) mma16816(acc[i][j], ah[i], bb[j]);
            #pragma unroll
            for (int i = 0; i < 2; i++)
                #pragma unroll
                for (int j = 0; j < 8; j++) mma16816(acc[i][j], al[i], bb[j]);
            #pragma unroll
            for (int p = 0; p < 4; p++) {
                uint32_t row = warpN + p * 16 + lrow;
                uint32_t off = row * 64 + (colb ^ ((row & 6) << 3));
                uint32_t r[4];
                ldsm4(r, sb + OFF_BL + off);
                bb[2 * p][0] = r[0]; bb[2 * p][1] = r[2];
                bb[2 * p + 1][0] = r[1]; bb[2 * p + 1][1] = r[3];
            }
            #pragma unroll
            for (int i = 0; i < 2; i++)
                #pragma unroll
                for (int j = 0; j < 8; j++) mma16816(acc[i][j], ah[i], bb[j]);
        }
    }

    // ---------- epilogue ----------
    #pragma unroll
    for (int i = 0; i < 2; i++) {
        const int m0 = mBase + warpM + i * 16 + (lane >> 2);
        #pragma unroll
        for (int j = 0; j < 8; j++) {
            const int n = nBase + warpN + j * 8 + (lane & 3) * 2;
            const float2 bb2 = *reinterpret_cast<const float2*>(&bias[n]);
            float v00 = acc[i][j][0] + bb2.x, v01 = acc[i][j][1] + bb2.y;
            float v10 = acc[i][j][2] + bb2.x, v11 = acc[i][j][3] + bb2.y;
            if (TANH) {
                v00 = tanh_fast(v00); v01 = tanh_fast(v01);
                v10 = tanh_fast(v10); v11 = tanh_fast(v11);
            }
            if (FP32OUT) {
                *reinterpret_cast<float2*>(&Cf[(size_t)m0 * N + n])       = make_float2(v00, v01);
                *reinterpret_cast<float2*>(&Cf[(size_t)(m0 + 8) * N + n]) = make_float2(v10, v11);
            } else {
                uint32_t hi, lo;
                split2(v00, v01, hi, lo);
                *reinterpret_cast<uint32_t*>(&Ch[(size_t)m0 * N + n]) = hi;
                *reinterpret_cast<uint32_t*>(&Cl[(size_t)m0 * N + n]) = lo;
                split2(v10, v11, hi, lo);
                *reinterpret_cast<uint32_t*>(&Ch[(size_t)(m0 + 8) * N + n]) = hi;
                *reinterpret_cast<uint32_t*>(&Cl[(size_t)(m0 + 8) * N + n]) = lo;
            }
        }
    }
}

// ---------- launch ----------
extern "C" void kernel_launch(void* const* d_in, const int* in_sizes, int n_in,
                              void* d_out, int out_size)
{
    const float* x  = (const float*)d_in[0];
    const float* W1 = (const float*)d_in[1];
    const float* b1 = (const float*)d_in[2];
    const float* W2 = (const float*)d_in[3];
    const float* b2 = (const float*)d_in[4];
    const float* W3 = (const float*)d_in[5];
    const float* b3 = (const float*)d_in[6];
    float* out = (float*)d_out;

    prep_x<<<(int)((size_t)BATCH * DIN / 4 / 256), 256>>>(x);
    prep_w<<<(int)((W1_SZ + 255) / 256), 256>>>(W1, DIN, HID, W1_OFF);
    prep_w<<<(int)((W2_SZ + 255) / 256), 256>>>(W2, HID, HID, W2_OFF);
    prep_w<<<(int)((W3_SZ + 255) / 256), 256>>>(W3, HID, DOUT, W3_OFF);

    cudaFuncSetAttribute(gemm_hmma<true,  false>,
                         cudaFuncAttributeMaxDynamicSharedMemorySize, SMEM_TOTAL);
    cudaFuncSetAttribute(gemm_hmma<false, true>,
                         cudaFuncAttributeMaxDynamicSharedMemorySize, SMEM_TOTAL);

    dim3 grid12(HID / 128, BATCH / 256);   // (4, 512)
    dim3 grid3 (DOUT / 128, BATCH / 256);  // (1, 512)

    gemm_hmma<true,  false><<<grid12, 512, SMEM_TOTAL>>>(0, W1_OFF, b1, 1, nullptr, HID, DIN);
    gemm_hmma<true,  false><<<grid12, 512, SMEM_TOTAL>>>(1, W2_OFF, b2, 2, nullptr, HID, HID);
    gemm_hmma<false, true ><<<grid3,  512, SMEM_TOTAL>>>(2, W3_OFF, b3, 0, out, DOUT, HID);
}

// round 9
// speedup vs baseline: 1.2433x; 1.1771x over previous
#include <cuda_runtime.h>
#include <cuda_bf16.h>
#include <math.h>
#include <stdint.h>

// x[131072,256] @ W1[256,512] -> tanh -> @W2[512,512] -> tanh -> @W3[512,128] (+biases).
// Fixed-point loop converges to F(x) within ~4e-7 abs => output == MLP forward.
constexpr int BATCH = 131072;
constexpr int DIN   = 256;
constexpr int HID   = 512;
constexpr int DOUT  = 128;

// ---------- device scratch (static; no runtime allocation allowed) ----------
__device__ __align__(256) __nv_bfloat16 g_xh[(size_t)BATCH * DIN];
__device__ __align__(256) __nv_bfloat16 g_xl[(size_t)BATCH * DIN];
__device__ __align__(256) __nv_bfloat16 g_h1h[(size_t)BATCH * HID];
__device__ __align__(256) __nv_bfloat16 g_h1l[(size_t)BATCH * HID];
__device__ __align__(256) __nv_bfloat16 g_h2h[(size_t)BATCH * HID];
__device__ __align__(256) __nv_bfloat16 g_h2l[(size_t)BATCH * HID];

constexpr size_t W1_OFF = 0;
constexpr size_t W1_SZ  = (size_t)HID * DIN;
constexpr size_t W2_OFF = W1_OFF + W1_SZ;
constexpr size_t W2_SZ  = (size_t)HID * HID;
constexpr size_t W3_OFF = W2_OFF + W2_SZ;
constexpr size_t W3_SZ  = (size_t)DOUT * HID;
__device__ __align__(256) __nv_bfloat16 g_wh[W1_SZ + W2_SZ + W3_SZ];
__device__ __align__(256) __nv_bfloat16 g_wl[W1_SZ + W2_SZ + W3_SZ];

// ---------- PTX helpers (compute_103-safe: NO tcgen05) ----------
__device__ __forceinline__ uint32_t smem_u32(const void* p) {
    uint32_t a;
    asm("{ .reg .u64 t; cvta.to.shared.u64 t, %1; cvt.u32.u64 %0, t; }" : "=r"(a) : "l"(p));
    return a;
}
__device__ __forceinline__ void cp16(uint32_t dst, const void* src) {
    asm volatile("cp.async.cg.shared.global [%0], [%1], 16;" :: "r"(dst), "l"(src));
}
__device__ __forceinline__ void cp_commit() { asm volatile("cp.async.commit_group;"); }
__device__ __forceinline__ void cp_wait1()  { asm volatile("cp.async.wait_group 1;"); }

__device__ __forceinline__ void ldsm4(uint32_t* r, uint32_t addr) {
    asm volatile("ldmatrix.sync.aligned.m8n8.x4.shared.b16 {%0,%1,%2,%3}, [%4];"
                 : "=r"(r[0]), "=r"(r[1]), "=r"(r[2]), "=r"(r[3]) : "r"(addr));
}
__device__ __forceinline__ void mma16816(float* d, const uint32_t* a, const uint32_t* b) {
    asm volatile("mma.sync.aligned.m16n8k16.row.col.f32.bf16.bf16.f32 "
                 "{%0,%1,%2,%3}, {%4,%5,%6,%7}, {%8,%9}, {%0,%1,%2,%3};"
                 : "+f"(d[0]), "+f"(d[1]), "+f"(d[2]), "+f"(d[3])
                 : "r"(a[0]), "r"(a[1]), "r"(a[2]), "r"(a[3]), "r"(b[0]), "r"(b[1]));
}

// fast accurate tanh: (e-1)/(e+1), e = 2^(2x*log2e). abs err ~1e-7.
__device__ __forceinline__ float tanh_fast(float x) {
    float xc = fminf(fmaxf(x, -15.0f), 15.0f);
    float e;
    asm("ex2.approx.f32 %0, %1;" : "=f"(e) : "f"(xc * 2.885390081777927f));
    float r;
    asm("rcp.approx.f32 %0, %1;" : "=f"(r) : "f"(e + 1.0f));
    return (e - 1.0f) * r;
}

__device__ __forceinline__ void split2(float v0, float v1, uint32_t& hi, uint32_t& lo) {
    __nv_bfloat16 h0 = __float2bfloat16(v0);
    __nv_bfloat16 h1 = __float2bfloat16(v1);
    __nv_bfloat16 l0 = __float2bfloat16(v0 - __bfloat162float(h0));
    __nv_bfloat16 l1 = __float2bfloat16(v1 - __bfloat162float(h1));
    hi = (uint32_t)__bfloat16_as_ushort(h0) | ((uint32_t)__bfloat16_as_ushort(h1) << 16);
    lo = (uint32_t)__bfloat16_as_ushort(l0) | ((uint32_t)__bfloat16_as_ushort(l1) << 16);
}

// ---------- merged prep: x split + all W split/transpose in ONE launch ----------
// Blocks [0, XB): x (4 floats/thread). Blocks [XB, XB+WB): weights.
constexpr int XB = (int)((size_t)BATCH * DIN / 4 / 256);          // 32768
constexpr int WTOT = (int)(W1_SZ + W2_SZ + W3_SZ);                // 458752
constexpr int WB = (WTOT + 255) / 256;                            // 1792

__global__ void prep_all(const float* __restrict__ x,
                         const float* __restrict__ W1,
                         const float* __restrict__ W2,
                         const float* __restrict__ W3)
{
    int b = blockIdx.x;
    if (b < XB) {
        size_t i = ((size_t)b * 256 + threadIdx.x) * 4;
        float4 v = *reinterpret_cast<const float4*>(x + i);
        uint2 hi, lo;
        split2(v.x, v.y, hi.x, lo.x);
        split2(v.z, v.w, hi.y, lo.y);
        *reinterpret_cast<uint2*>(&g_xh[i]) = hi;
        *reinterpret_cast<uint2*>(&g_xl[i]) = lo;
    } else {
        int idx = (b - XB) * 256 + threadIdx.x;                   // global split index
        if (idx >= WTOT) return;
        const float* W; int K, N, loc;
        if (idx < (int)W2_OFF)      { W = W1; K = DIN; N = HID;  loc = idx; }
        else if (idx < (int)W3_OFF) { W = W2; K = HID; N = HID;  loc = idx - (int)W2_OFF; }
        else                        { W = W3; K = HID; N = DOUT; loc = idx - (int)W3_OFF; }
        int n = loc / K;
        int k = loc - n * K;
        float v = W[(size_t)k * N + n];
        __nv_bfloat16 h = __float2bfloat16(v);
        g_wh[idx] = h;
        g_wl[idx] = __float2bfloat16(v - __bfloat162float(h));
    }
}

// ---------- main GEMM: 128x128 tile, BK=32, 3-stage cp.async, single sync/iter ----------
// SMEM per stage: AH 8KB | AL 8KB | BH 8KB | BL 8KB = 32KB; 3 stages = 96KB -> 2 CTAs/SM.
constexpr uint32_t OFF_AH = 0;
constexpr uint32_t OFF_AL = 8192;
constexpr uint32_t OFF_BH = 16384;
constexpr uint32_t OFF_BL = 24576;
constexpr uint32_t STAGE  = 32768;
constexpr int SMEM_TOTAL  = 3 * STAGE;   // 98304 (96KB) -> 2 CTAs/SM (192KB/SM)

template<bool TANH, bool FP32OUT>
__global__ __launch_bounds__(256, 2)
void gemm_hmma(int aSel, size_t wOff, const float* __restrict__ bias,
               int cSel, float* __restrict__ Cf, int N, int K)
{
    const __nv_bfloat16 *Ah, *Al;
    if      (aSel == 0) { Ah = g_xh;  Al = g_xl;  }
    else if (aSel == 1) { Ah = g_h1h; Al = g_h1l; }
    else                { Ah = g_h2h; Al = g_h2l; }
    __nv_bfloat16 *Ch = nullptr, *Cl = nullptr;
    if      (cSel == 1) { Ch = g_h1h; Cl = g_h1l; }
    else if (cSel == 2) { Ch = g_h2h; Cl = g_h2l; }
    const __nv_bfloat16* Wh = g_wh + wOff;
    const __nv_bfloat16* Wl = g_wl + wOff;

    extern __shared__ char smem[];
    const uint32_t sbase = smem_u32(smem);
    const int tid  = threadIdx.x;
    const int wid  = tid >> 5;
    const int lane = tid & 31;
    const int mBase = blockIdx.y * 128;
    const int nBase = blockIdx.x * 128;
    const int warpM = (wid >> 1) * 32;     // 4 warp-rows x 32
    const int warpN = (wid & 1) * 64;      // 2 warp-cols x 64
    const int NC = K / 32;

    // loader mapping: 256 threads, 16B chunks, row stride 64B (32 bf16), 128 rows/region
    const int lr = tid >> 2;               // 0..63 (two passes of 64 rows)
    const int lj = tid & 3;
    const uint32_t swj = (uint32_t)lj * 16;
    auto so = [&](uint32_t row) { return row * 64 + (swj ^ ((row & 6) << 3)); };

    auto loadChunk = [&](int kc, int s) {
        const uint32_t sb = sbase + (uint32_t)s * STAGE;
        const size_t colOff = (size_t)kc * 32 + lj * 8;
        #pragma unroll
        for (int i = 0; i < 2; i++) {
            uint32_t row = (uint32_t)(lr + i * 64);
            const size_t ga = (size_t)(mBase + row) * K + colOff;
            const size_t gb = (size_t)(nBase + row) * K + colOff;
            cp16(sb + OFF_AH + so(row), Ah + ga);
            cp16(sb + OFF_AL + so(row), Al + ga);
            cp16(sb + OFF_BH + so(row), Wh + gb);
            cp16(sb + OFF_BL + so(row), Wl + gb);
        }
    };

    float acc[2][8][4];
    #pragma unroll
    for (int i = 0; i < 2; i++)
        #pragma unroll
        for (int j = 0; j < 8; j++)
            #pragma unroll
            for (int q = 0; q < 4; q++) acc[i][j][q] = 0.0f;

    const int lrow = lane & 15, lhi = lane >> 4;

    loadChunk(0, 0); cp_commit();
    loadChunk(1, 1); cp_commit();

    for (int c = 0; c < NC; c++) {
        cp_wait1();                    // chunk c resident (<=1 group pending)
        __syncthreads();               // all warps done reading buffer (c+2)%3 (iter c-1)
        if (c + 2 < NC) loadChunk(c + 2, (c + 2) % 3);
        cp_commit();                   // commit every iter (possibly empty) to keep counts

        const uint32_t sb = sbase + (uint32_t)(c % 3) * STAGE;
        #pragma unroll
        for (int ks = 0; ks < 2; ks++) {
            const uint32_t colb = ks * 32 + lhi * 16;
            uint32_t ah[2][4], al[2][4], bb[8][2];
            #pragma unroll
            for (int i = 0; i < 2; i++) {
                uint32_t row = warpM + i * 16 + lrow;
                uint32_t off = row * 64 + (colb ^ ((row & 6) << 3));
                ldsm4(ah[i], sb + OFF_AH + off);
                ldsm4(al[i], sb + OFF_AL + off);
            }
            #pragma unroll
            for (int p = 0; p < 4; p++) {
                uint32_t row = warpN + p * 16 + lrow;
                uint32_t off = row * 64 + (colb ^ ((row & 6) << 3));
                uint32_t r[4];
                ldsm4(r, sb + OFF_BH + off);
                bb[2 * p][0] = r[0]; bb[2 * p][1] = r[2];
                bb[2 * p + 1][0] = r[1]; bb[2 * p + 1][1] = r[3];
            }
            #pragma unroll
            for (int i = 0; i < 2; i++)
                #pragma unroll
                for (int j = 0; j < 8; j++) mma16816(acc[i][j], ah[i], bb[j]);
            #pragma unroll
            for (int i = 0; i < 2; i++)
                #pragma unroll
                for (int j = 0; j < 8; j++) mma16816(acc[i][j], al[i], bb[j]);
            #pragma unroll
            for (int p = 0; p < 4; p++) {
                uint32_t row = warpN + p * 16 + lrow;
                uint32_t off = row * 64 + (colb ^ ((row & 6) << 3));
                uint32_t r[4];
                ldsm4(r, sb + OFF_BL + off);
                bb[2 * p][0] = r[0]; bb[2 * p][1] = r[2];
                bb[2 * p + 1][0] = r[1]; bb[2 * p + 1][1] = r[3];
            }
            #pragma unroll
            for (int i = 0; i < 2; i++)
                #pragma unroll
                for (int j = 0; j < 8; j++) mma16816(acc[i][j], ah[i], bb[j]);
        }
    }

    // ---------- epilogue ----------
    #pragma unroll
    for (int i = 0; i < 2; i++) {
        const int m0 = mBase + warpM + i * 16 + (lane >> 2);
        #pragma unroll
        for (int j = 0; j < 8; j++) {
            const int n = nBase + warpN + j * 8 + (lane & 3) * 2;
            const float2 bb2 = *reinterpret_cast<const float2*>(&bias[n]);
            float v00 = acc[i][j][0] + bb2.x, v01 = acc[i][j][1] + bb2.y;
            float v10 = acc[i][j][2] + bb2.x, v11 = acc[i][j][3] + bb2.y;
            if (TANH) {
                v00 = tanh_fast(v00); v01 = tanh_fast(v01);
                v10 = tanh_fast(v10); v11 = tanh_fast(v11);
            }
            if (FP32OUT) {
                *reinterpret_cast<float2*>(&Cf[(size_t)m0 * N + n])       = make_float2(v00, v01);
                *reinterpret_cast<float2*>(&Cf[(size_t)(m0 + 8) * N + n]) = make_float2(v10, v11);
            } else {
                uint32_t hi, lo;
                split2(v00, v01, hi, lo);
                *reinterpret_cast<uint32_t*>(&Ch[(size_t)m0 * N + n]) = hi;
                *reinterpret_cast<uint32_t*>(&Cl[(size_t)m0 * N + n]) = lo;
                split2(v10, v11, hi, lo);
                *reinterpret_cast<uint32_t*>(&Ch[(size_t)(m0 + 8) * N + n]) = hi;
                *reinterpret_cast<uint32_t*>(&Cl[(size_t)(m0 + 8) * N + n]) = lo;
            }
        }
    }
}

// ---------- launch ----------
extern "C" void kernel_launch(void* const* d_in, const int* in_sizes, int n_in,
                              void* d_out, int out_size)
{
    const float* x  = (const float*)d_in[0];
    const float* W1 = (const float*)d_in[1];
    const float* b1 = (const float*)d_in[2];
    const float* W2 = (const float*)d_in[3];
    const float* b2 = (const float*)d_in[4];
    const float* W3 = (const float*)d_in[5];
    const float* b3 = (const float*)d_in[6];
    float* out = (float*)d_out;

    prep_all<<<XB + WB, 256>>>(x, W1, W2, W3);

    cudaFuncSetAttribute(gemm_hmma<true,  false>,
                         cudaFuncAttributeMaxDynamicSharedMemorySize, SMEM_TOTAL);
    cudaFuncSetAttribute(gemm_hmma<false, true>,
                         cudaFuncAttributeMaxDynamicSharedMemorySize, SMEM_TOTAL);

    dim3 grid12(HID / 128, BATCH / 128);   // (4, 1024)
    dim3 grid3 (DOUT / 128, BATCH / 128);  // (1, 1024)

    gemm_hmma<true,  false><<<grid12, 256, SMEM_TOTAL>>>(0, W1_OFF, b1, 1, nullptr, HID, DIN);
    gemm_hmma<true,  false><<<grid12, 256, SMEM_TOTAL>>>(1, W2_OFF, b2, 2, nullptr, HID, HID);
    gemm_hmma<false, true ><<<grid3,  256, SMEM_TOTAL>>>(2, W3_OFF, b3, 0, out, DOUT, HID);
}